// round 16
// baseline (speedup 1.0000x reference)
#include <cuda_runtime.h>
#include <cuda_bf16.h>
#include <cstdio>
#include <cstdint>

#define D 128
#define ESZ 20
#define MAX_NODES 20000
#define MAX_EDGES 600000
#define CUTOFF 5.0f

// ---------------- scratch (static device bss; no allocations) ----------------
__device__ __align__(16) float g_h1 [MAX_NODES * D];
__device__ __align__(16) float g_so [MAX_NODES * 3 * D];
__device__ __align__(16) float g_s  [MAX_NODES * D];
__device__ __align__(16) float g_v  [MAX_NODES * 3 * D];
__device__ __align__(16) float g_Uv [MAX_NODES * 3 * D];
__device__ __align__(16) float g_Vv [MAX_NODES * 3 * D];
__device__ __align__(16) float g_cat[MAX_NODES * 2 * D];
__device__ __align__(16) float g_ip [MAX_NODES * D];
__device__ __align__(16) float g_h2 [MAX_NODES * D];
__device__ __align__(16) float g_a  [MAX_NODES * 3 * D];

// ---------------- helpers ----------------
__device__ __forceinline__ void red_add_v4(float* addr, float4 v) {
    asm volatile("red.global.add.v4.f32 [%0], {%1, %2, %3, %4};"
                 :: "l"(addr), "f"(v.x), "f"(v.y), "f"(v.z), "f"(v.w) : "memory");
}
__device__ __forceinline__ void red_add_v2(float* addr, float2 v) {
    asm volatile("red.global.add.v2.f32 [%0], {%1, %2};"
                 :: "l"(addr), "f"(v.x), "f"(v.y) : "memory");
}
__device__ __forceinline__ float silu_f(float x) {
    return x / (1.0f + __expf(-x));
}
__device__ __forceinline__ uint32_t f2tf32(float f) {
    uint32_t r;
    asm("cvt.rna.tf32.f32 %0, %1;" : "=r"(r) : "f"(f));
    return r;
}
__device__ __forceinline__ void mma_tf32(float c[4],
    uint32_t a0, uint32_t a1, uint32_t a2, uint32_t a3,
    uint32_t b0, uint32_t b1)
{
    asm volatile(
        "mma.sync.aligned.m16n8k8.row.col.f32.tf32.tf32.f32 "
        "{%0,%1,%2,%3}, {%4,%5,%6,%7}, {%8,%9}, {%0,%1,%2,%3};"
        : "+f"(c[0]), "+f"(c[1]), "+f"(c[2]), "+f"(c[3])
        : "r"(a0), "r"(a1), "r"(a2), "r"(a3), "r"(b0), "r"(b1));
}

// ---------------- init: copy node states into accumulators ----------------
__global__ void init_copy_kernel(const float* __restrict__ ns, const float* __restrict__ nv, int n) {
    int tid = blockIdx.x * blockDim.x + threadIdx.x;
    int stride = gridDim.x * blockDim.x;
    const float4* ns4 = (const float4*)ns;
    const float4* nv4 = (const float4*)nv;
    float4* s4 = (float4*)g_s;
    float4* v4 = (float4*)g_v;
    int cs = n * (D / 4);
    int cv = n * (3 * D / 4);
    for (int i = tid; i < cs; i += stride) s4[i] = ns4[i];
    for (int i = tid; i < cv; i += stride) v4[i] = nv4[i];
}

// ---------------- tf32 tensor-core GEMM: C = act(A[MxK] @ B[KxN] + bias) ----------------
template<bool SILU, bool HASBIAS>
__global__ __launch_bounds__(256) void mma_gemm_kernel(
    const float* __restrict__ A, const float* __restrict__ B,
    const float* __restrict__ bias, float* __restrict__ C,
    int M, int N, int K)
{
    const int BM = 128, BN = 64, BK = 16;
    __shared__ __align__(16) float As[BK][BM + 8];
    __shared__ __align__(16) float Bs[BK][BN + 8];
    int t = threadIdx.x;
    int lane = t & 31;
    int warp = t >> 5;
    int g = lane >> 2;
    int tig = lane & 3;
    int wm = warp & 3;
    int wn = warp >> 2;
    int m0 = blockIdx.x * BM;
    int n0 = blockIdx.y * BN;

    float c[2][4][4];
    #pragma unroll
    for (int mt = 0; mt < 2; mt++)
        #pragma unroll
        for (int nt = 0; nt < 4; nt++)
            #pragma unroll
            for (int i = 0; i < 4; i++) c[mt][nt][i] = 0.0f;

    for (int k0 = 0; k0 < K; k0 += BK) {
        #pragma unroll
        for (int it = 0; it < 2; it++) {
            int l = t + 256 * it;
            int row = l >> 2;
            int kc = (l & 3) * 4;
            float4 v = make_float4(0.f, 0.f, 0.f, 0.f);
            int gr = m0 + row;
            if (gr < M) v = *(const float4*)&A[(size_t)gr * K + k0 + kc];
            As[kc + 0][row] = v.x;
            As[kc + 1][row] = v.y;
            As[kc + 2][row] = v.z;
            As[kc + 3][row] = v.w;
        }
        {
            int row = t >> 4;
            int nc = (t & 15) * 4;
            *(float4*)&Bs[row][nc] = *(const float4*)&B[(size_t)(k0 + row) * N + n0 + nc];
        }
        __syncthreads();

        #pragma unroll
        for (int k8 = 0; k8 < BK; k8 += 8) {
            uint32_t a[2][4];
            #pragma unroll
            for (int mt = 0; mt < 2; mt++) {
                int mrow = wm * 32 + mt * 16;
                a[mt][0] = f2tf32(As[k8 + tig][mrow + g]);
                a[mt][1] = f2tf32(As[k8 + tig][mrow + g + 8]);
                a[mt][2] = f2tf32(As[k8 + tig + 4][mrow + g]);
                a[mt][3] = f2tf32(As[k8 + tig + 4][mrow + g + 8]);
            }
            uint32_t b[4][2];
            #pragma unroll
            for (int nt = 0; nt < 4; nt++) {
                int ncol = wn * 32 + nt * 8;
                b[nt][0] = f2tf32(Bs[k8 + tig][ncol + g]);
                b[nt][1] = f2tf32(Bs[k8 + tig + 4][ncol + g]);
            }
            #pragma unroll
            for (int mt = 0; mt < 2; mt++)
                #pragma unroll
                for (int nt = 0; nt < 4; nt++)
                    mma_tf32(c[mt][nt], a[mt][0], a[mt][1], a[mt][2], a[mt][3],
                             b[nt][0], b[nt][1]);
        }
        __syncthreads();
    }

    #pragma unroll
    for (int mt = 0; mt < 2; mt++) {
        #pragma unroll
        for (int nt = 0; nt < 4; nt++) {
            int row0 = m0 + wm * 32 + mt * 16 + g;
            int row1 = row0 + 8;
            int col = n0 + wn * 32 + nt * 8 + 2 * tig;
            float2 bv = make_float2(0.f, 0.f);
            if (HASBIAS) bv = *(const float2*)&bias[col];
            if (row0 < M) {
                float2 o;
                o.x = c[mt][nt][0] + bv.x;
                o.y = c[mt][nt][1] + bv.y;
                if (SILU) { o.x = silu_f(o.x); o.y = silu_f(o.y); }
                *(float2*)&C[(size_t)row0 * N + col] = o;
            }
            if (row1 < M) {
                float2 o;
                o.x = c[mt][nt][2] + bv.x;
                o.y = c[mt][nt][3] + bv.y;
                if (SILU) { o.x = silu_f(o.x); o.y = silu_f(o.y); }
                *(float2*)&C[(size_t)row1 * N + col] = o;
            }
        }
    }
}

// ---------------- fused edge kernel (v10: tensor-core filter) ----------------
// 192 threads (6 warps), EB=16 edges/batch (one m16 tile).
// Filter GEMM FW[16,384] = ES[16,24] @ WfX[24,384] via mma.m16n8k8.tf32, where
// ES col 20 = 1.0 and WfX row 20 = bf (bias folded), rows 21-23 = 0.
// Warp w owns cols [64w, 64w+64): 8 n8-tiles x 3 k8-steps; Wf frags in 48 regs.
// Epilogue: fo = FW * fc * so[src]; warps 0-3 -> fo_sh (gn/ge), warps 4-5 ->
// red.v2 to g_s (ms). Phase 2 identical to proven v8/v9 body.
#define EB 16
#define KPAD 24
__global__ void __launch_bounds__(192, 3) edge_kernel(
    const float* __restrict__ es_g, const float* __restrict__ ev_g,
    const float* __restrict__ norms, const int* __restrict__ eidx,
    const float* __restrict__ Wf, const float* __restrict__ bf,
    const float* __restrict__ nsv, int E)
{
    __shared__ __align__(16) float es_sh[2][EB][KPAD];
    __shared__ __align__(16) float fo_sh[EB][2 * D];   // gn[128], ge[128]
    __shared__ int   src_sh[2][EB], dst_sh[2][EB];
    __shared__ float ev_sh[2][EB][3];
    __shared__ float fc_sh[2][EB];

    int t = threadIdx.x;
    int w = t >> 5;
    int lane = t & 31;
    int g = lane >> 2;       // 0..7
    int tig = lane & 3;      // 0..3

    // B fragments: Wf (+bias row 20) for owned 64-col slice, tf32 in regs
    uint32_t bw[8][3][2];
    #pragma unroll
    for (int nt = 0; nt < 8; nt++) {
        int col = w * 64 + nt * 8 + g;
        #pragma unroll
        for (int ks = 0; ks < 3; ks++) {
            int ka = ks * 8 + tig;
            int kb = ka + 4;
            float va = (ka < 20) ? __ldg(&Wf[ka * 384 + col]) : (ka == 20 ? __ldg(&bf[col]) : 0.f);
            float vb = (kb < 20) ? __ldg(&Wf[kb * 384 + col]) : (kb == 20 ? __ldg(&bf[col]) : 0.f);
            bw[nt][ks][0] = f2tf32(va);
            bw[nt][ks][1] = f2tf32(vb);
        }
    }

    int nbatch = (E + EB - 1) / EB;
    int stride = gridDim.x;
    int b = blockIdx.x;
    if (b >= nbatch) return;
    int cur = 0;

    // ---- prologue: stage first batch into buffer 0 ----
    {
        int e0 = b * EB;
        int ecount = min(EB, E - e0);
        if (t < EB * 6) {          // 16 edges x 6 float4 (24 cols)
            int e = t / 6, q = t % 6;
            float4 v = make_float4(0.f, 0.f, 0.f, 0.f);
            if (q < 5) {
                if (e < ecount)
                    v = __ldg(&((const float4*)&es_g[(size_t)(e0 + e) * ESZ])[q]);
            } else {
                v = make_float4(1.f, 0.f, 0.f, 0.f);   // bias row selector
            }
            ((float4*)&es_sh[0][e][0])[q] = v;
        }
        if (t >= 96 && t < 96 + EB) {
            int l = t - 96;
            if (l < ecount) {
                int ge_ = e0 + l;
                src_sh[0][l] = eidx[2 * ge_];
                dst_sh[0][l] = eidx[2 * ge_ + 1];
                ev_sh[0][l][0] = ev_g[3 * ge_];
                ev_sh[0][l][1] = ev_g[3 * ge_ + 1];
                ev_sh[0][l][2] = ev_g[3 * ge_ + 2];
                float nrm = norms[ge_];
                fc_sh[0][l] = (nrm < CUTOFF) ? 0.5f * (cospif(nrm / CUTOFF) + 1.0f) : 0.0f;
            } else {
                src_sh[0][l] = 0; dst_sh[0][l] = 0;
                ev_sh[0][l][0] = ev_sh[0][l][1] = ev_sh[0][l][2] = 0.f;
                fc_sh[0][l] = 0.f;
            }
        }
    }
    __syncthreads();

    for (; b < nbatch; b += stride, cur ^= 1) {
        int e0 = b * EB;
        int ecount = min(EB, E - e0);
        int bn = b + stride;
        bool have_next = (bn < nbatch);
        int ecn = have_next ? min(EB, E - bn * EB) : 0;

        // ---- issue next batch's loads into registers ----
        float4 r_es = make_float4(0.f, 0.f, 0.f, 0.f);
        int   r_src = 0, r_dst = 0;
        float r_ev0 = 0.f, r_ev1 = 0.f, r_ev2 = 0.f, r_fc = 0.f;
        if (have_next) {
            if (t < EB * 6) {
                int e = t / 6, q = t % 6;
                if (q < 5) {
                    if (e < ecn)
                        r_es = __ldg(&((const float4*)&es_g[(size_t)(bn * EB + e) * ESZ])[q]);
                } else {
                    r_es = make_float4(1.f, 0.f, 0.f, 0.f);
                }
            }
            if (t >= 96 && t < 96 + EB) {
                int l = t - 96;
                if (l < ecn) {
                    int ge_ = bn * EB + l;
                    r_src = __ldg(&eidx[2 * ge_]);
                    r_dst = __ldg(&eidx[2 * ge_ + 1]);
                    r_ev0 = __ldg(&ev_g[3 * ge_]);
                    r_ev1 = __ldg(&ev_g[3 * ge_ + 1]);
                    r_ev2 = __ldg(&ev_g[3 * ge_ + 2]);
                    float nrm = __ldg(&norms[ge_]);
                    r_fc = (nrm < CUTOFF) ? 0.5f * (cospif(nrm / CUTOFF) + 1.0f) : 0.0f;
                }
            }
        }

        // ---- phase 1a: filter GEMM via tensor cores ----
        float cacc[8][4];
        #pragma unroll
        for (int nt = 0; nt < 8; nt++)
            #pragma unroll
            for (int i = 0; i < 4; i++) cacc[nt][i] = 0.0f;

        #pragma unroll
        for (int ks = 0; ks < 3; ks++) {
            int k0 = ks * 8;
            uint32_t a0 = f2tf32(es_sh[cur][g][k0 + tig]);
            uint32_t a1 = f2tf32(es_sh[cur][g + 8][k0 + tig]);
            uint32_t a2 = f2tf32(es_sh[cur][g][k0 + tig + 4]);
            uint32_t a3 = f2tf32(es_sh[cur][g + 8][k0 + tig + 4]);
            #pragma unroll
            for (int nt = 0; nt < 8; nt++)
                mma_tf32(cacc[nt], a0, a1, a2, a3, bw[nt][ks][0], bw[nt][ks][1]);
        }

        // ---- phase 1b: scale by fc * so and distribute ----
        {
            float fc0 = fc_sh[cur][g];
            float fc1 = fc_sh[cur][g + 8];
            int src0 = src_sh[cur][g];
            int src1 = src_sh[cur][g + 8];
            int dst0 = dst_sh[cur][g];
            int dst1 = dst_sh[cur][g + 8];
            #pragma unroll
            for (int nt = 0; nt < 8; nt++) {
                int col = w * 64 + nt * 8 + 2 * tig;
                float2 so0 = __ldg((const float2*)&g_so[(size_t)src0 * 384 + col]);
                float2 so1 = __ldg((const float2*)&g_so[(size_t)src1 * 384 + col]);
                float2 fo0, fo1;
                fo0.x = cacc[nt][0] * fc0 * so0.x;
                fo0.y = cacc[nt][1] * fc0 * so0.y;
                fo1.x = cacc[nt][2] * fc1 * so1.x;
                fo1.y = cacc[nt][3] * fc1 * so1.y;
                if (w < 4) {
                    *(float2*)&fo_sh[g][col]     = fo0;
                    *(float2*)&fo_sh[g + 8][col] = fo1;
                } else {
                    red_add_v2(&g_s[(size_t)dst0 * D + col - 256], fo0);
                    red_add_v2(&g_s[(size_t)dst1 * D + col - 256], fo1);
                }
            }
        }

        // ---- commit next batch's staged data ----
        if (have_next) {
            int nxt = cur ^ 1;
            if (t < EB * 6) {
                int e = t / 6, q = t % 6;
                ((float4*)&es_sh[nxt][e][0])[q] = r_es;
            }
            if (t >= 96 && t < 96 + EB) {
                int l = t - 96;
                src_sh[nxt][l] = r_src;
                dst_sh[nxt][l] = r_dst;
                ev_sh[nxt][l][0] = r_ev0;
                ev_sh[nxt][l][1] = r_ev1;
                ev_sh[nxt][l][2] = r_ev2;
                fc_sh[nxt][l] = r_fc;
            }
        }
        __syncthreads();

        // ---- phase 2: vector messages + scatter (proven body) ----
        {
            int s = lane;            // 0..31: float4 slot
            int grp = w;             // 0..5
            #pragma unroll
            for (int ee = 0; ee < 3; ee++) {
                int e = grp + 6 * ee;
                if (e >= ecount || e >= EB) continue;
                int dst = dst_sh[cur][e];
                int src = src_sh[cur][e];
                float4 gn = *(float4*)&fo_sh[e][4 * s];
                float4 ge = *(float4*)&fo_sh[e][D + 4 * s];
                #pragma unroll
                for (int c = 0; c < 3; c++) {
                    float evc = ev_sh[cur][e][c];
                    float4 nv = __ldg((const float4*)&nsv[((size_t)src * 3 + c) * D + 4 * s]);
                    float4 mv;
                    mv.x = fmaf(nv.x, gn.x, ge.x * evc);
                    mv.y = fmaf(nv.y, gn.y, ge.y * evc);
                    mv.z = fmaf(nv.z, gn.z, ge.z * evc);
                    mv.w = fmaf(nv.w, gn.w, ge.w * evc);
                    red_add_v4(&g_v[((size_t)dst * 3 + c) * D + 4 * s], mv);
                }
            }
        }
        __syncthreads();
    }
}

// ---------------- per-node: Vv_sq, ip, concat ----------------
__global__ void vsq_ip_cat_kernel(int n) {
    int node = blockIdx.x;
    int i = threadIdx.x;  // 128
    float vsq = 0.f, ipv = 0.f;
    #pragma unroll
    for (int c = 0; c < 3; c++) {
        float u = g_Uv[((size_t)node * 3 + c) * D + i];
        float w = g_Vv[((size_t)node * 3 + c) * D + i];
        vsq += w * w;
        ipv += u * w;
    }
    g_cat[(size_t)node * 256 + i]       = g_s[(size_t)node * D + i];
    g_cat[(size_t)node * 256 + D + i]   = vsq;
    g_ip[(size_t)node * D + i]          = ipv;
}

// ---------------- final elementwise ----------------
__global__ void final_kernel(float* __restrict__ out, int n) {
    int node = blockIdx.x;
    int i = threadIdx.x;  // 128
    const float* a = &g_a[(size_t)node * 384];
    float a_ss = a[i];
    float a_sv = a[D + i];
    float a_vv = a[2 * D + i];
    out[(size_t)node * D + i] =
        g_s[(size_t)node * D + i] + a_ss + a_sv * g_ip[(size_t)node * D + i];
    float* vout = out + (size_t)n * D;
    #pragma unroll
    for (int c = 0; c < 3; c++) {
        size_t idx = ((size_t)node * 3 + c) * D + i;
        vout[idx] = g_v[idx] + a_vv * g_Uv[idx];
    }
}

// ---------------- launch ----------------
extern "C" void kernel_launch(void* const* d_in, const int* in_sizes, int n_in,
                              void* d_out, int out_size) {
    const float* ns  = (const float*)d_in[0];
    const float* nv  = (const float*)d_in[1];
    const float* es  = (const float*)d_in[2];
    const float* ev  = (const float*)d_in[3];
    const float* en  = (const float*)d_in[4];
    const int*   ei  = (const int*)  d_in[5];
    const float* Wf  = (const float*)d_in[6];
    const float* bf  = (const float*)d_in[7];
    const float* Wm1 = (const float*)d_in[8];
    const float* bm1 = (const float*)d_in[9];
    const float* Wm2 = (const float*)d_in[10];
    const float* bm2 = (const float*)d_in[11];
    const float* WU  = (const float*)d_in[12];
    const float* WV  = (const float*)d_in[13];
    const float* Wa1 = (const float*)d_in[14];
    const float* ba1 = (const float*)d_in[15];
    const float* Wa2 = (const float*)d_in[16];
    const float* ba2 = (const float*)d_in[17];

    int n = in_sizes[0] / D;
    int E = in_sizes[4];
    float* out = (float*)d_out;

    float *p_h1, *p_so, *p_v, *p_Uv, *p_Vv, *p_cat, *p_h2, *p_a;
    cudaGetSymbolAddress((void**)&p_h1,  g_h1);
    cudaGetSymbolAddress((void**)&p_so,  g_so);
    cudaGetSymbolAddress((void**)&p_v,   g_v);
    cudaGetSymbolAddress((void**)&p_Uv,  g_Uv);
    cudaGetSymbolAddress((void**)&p_Vv,  g_Vv);
    cudaGetSymbolAddress((void**)&p_cat, g_cat);
    cudaGetSymbolAddress((void**)&p_h2,  g_h2);
    cudaGetSymbolAddress((void**)&p_a,   g_a);

    // 1. init accumulators s = ns, v = nv
    init_copy_kernel<<<2048, 256>>>(ns, nv, n);

    // 2. H1 = silu(ns @ Wm1 + bm1)
    {
        dim3 grid((n + 127) / 128, 128 / 64);
        mma_gemm_kernel<true, true><<<grid, 256>>>(ns, Wm1, bm1, p_h1, n, 128, 128);
    }
    // 3. SO = H1 @ Wm2 + bm2
    {
        dim3 grid((n + 127) / 128, 384 / 64);
        mma_gemm_kernel<false, true><<<grid, 256>>>(p_h1, Wm2, bm2, p_so, n, 384, 128);
    }
    // 4. fused edge kernel (tensor-core filter, pipelined)
    {
        int nbatch = (E + EB - 1) / EB;
        int grid = nbatch < 2664 ? nbatch : 2664;   // 148 SMs x 3 CTAs x 6 waves
        edge_kernel<<<grid, 192>>>(es, ev, en, ei, Wf, bf, nv, E);
    }
    // 5/6. Uv = v @ WU, Vv = v @ WV
    {
        dim3 grid((3 * n + 127) / 128, 128 / 64);
        mma_gemm_kernel<false, false><<<grid, 256>>>(p_v, WU, nullptr, p_Uv, 3 * n, 128, 128);
        mma_gemm_kernel<false, false><<<grid, 256>>>(p_v, WV, nullptr, p_Vv, 3 * n, 128, 128);
    }
    // 7. Vv_sq, ip, cat
    vsq_ip_cat_kernel<<<n, 128>>>(n);

    // 8. H2 = silu(cat @ Wa1 + ba1)
    {
        dim3 grid((n + 127) / 128, 128 / 64);
        mma_gemm_kernel<true, true><<<grid, 256>>>(p_cat, Wa1, ba1, p_h2, n, 128, 256);
    }
    // 9. A = H2 @ Wa2 + ba2
    {
        dim3 grid((n + 127) / 128, 384 / 64);
        mma_gemm_kernel<false, true><<<grid, 256>>>(p_h2, Wa2, ba2, p_a, n, 384, 128);
    }
    // 10. final
    final_kernel<<<n, 128>>>(out, n);
}